// round 12
// baseline (speedup 1.0000x reference)
#include <cuda_runtime.h>
#include <cuda_fp16.h>
#include <math.h>
#include <stdint.h>

// Problem dims
#define Bsz  256
#define Tsz  256
#define INsz 4
#define HPsz 64
#define Esz  512
#define Hsz  1024
#define Dsz  4
#define ROWS (Bsz * Tsz)   // 65536
#define HRWS (ROWS / 2)    // rows per slice (128 batches)

// ---------------------------------------------------------------------------
// Scratch (device globals; no allocation allowed)
// ---------------------------------------------------------------------------
__device__ float  g_x  [(size_t)ROWS * Esz];
__device__ __half g_xhi[(size_t)ROWS * Esz];
__device__ __half g_xlo[(size_t)ROWS * Esz];
__device__ float  g_h1 [(size_t)ROWS * Hsz];
__device__ __half g_spk[(size_t)ROWS * Hsz];
__device__ float  g_h2 [(size_t)ROWS * Esz];
__device__ float  g_psum[(size_t)ROWS * 8];   // stride 8 for BOTH gemms
__device__ float  g_psq [(size_t)ROWS * 8];
__device__ __half g_w1hi[(size_t)Dsz * Hsz * Esz];
__device__ __half g_w1lo[(size_t)Dsz * Hsz * Esz];
__device__ __half g_w2hi[(size_t)Dsz * Esz * Hsz];
__device__ __half g_w2lo[(size_t)Dsz * Esz * Hsz];

// ---------------------------------------------------------------------------
// Helpers
// ---------------------------------------------------------------------------
__device__ __forceinline__ uint32_t sw128(uint32_t b) { return b ^ ((b >> 3) & 0x70); }

__device__ __forceinline__ uint32_t s2u(const void* p) {
    uint32_t a;
    asm("{ .reg .u64 t; cvta.to.shared.u64 t, %1; cvt.u32.u64 %0, t; }" : "=r"(a) : "l"(p));
    return a;
}

__device__ __forceinline__ void cp16(uint32_t saddr, const void* g) {
    asm volatile("cp.async.cg.shared.global [%0], [%1], 16;" :: "r"(saddr), "l"(g));
}

#define LDSM4(r0, r1, r2, r3, addr)                                           \
    asm volatile("ldmatrix.sync.aligned.m8n8.x4.shared.b16 {%0,%1,%2,%3}, [%4];" \
                 : "=r"(r0), "=r"(r1), "=r"(r2), "=r"(r3) : "r"(addr))

#define MMA16816(d, a, b)                                                     \
    asm volatile(                                                             \
        "mma.sync.aligned.m16n8k16.row.col.f32.f16.f16.f32 "                  \
        "{%0,%1,%2,%3},{%4,%5,%6,%7},{%8,%9},{%0,%1,%2,%3};"                  \
        : "+f"((d)[0]), "+f"((d)[1]), "+f"((d)[2]), "+f"((d)[3])              \
        : "r"((a)[0]), "r"((a)[1]), "r"((a)[2]), "r"((a)[3]),                 \
          "r"((b)[0]), "r"((b)[1]))

// ---------------------------------------------------------------------------
// Split+transpose weights
// ---------------------------------------------------------------------------
__global__ void split_w(const float* __restrict__ W, __half* __restrict__ hi,
                        __half* __restrict__ lo, int K, int N) {
    int idx = blockIdx.x * blockDim.x + threadIdx.x;
    if (idx >= K * N) return;
    size_t lofs = (size_t)blockIdx.y * K * N;
    int k = idx / N, n = idx % N;
    float w = W[lofs + idx];
    __half h = __float2half_rn(w);
    hi[lofs + (size_t)n * K + k] = h;
    lo[lofs + (size_t)n * K + k] = __float2half_rn(w - __half2float(h));
}

// ---------------------------------------------------------------------------
// smem geometry
// ---------------------------------------------------------------------------
template <int TERMS> struct G2 {
    static constexpr int AHI = 0;
    static constexpr int ALO = 32768;
    static constexpr int BHI = (TERMS == 3) ? 65536 : 32768;
    static constexpr int BLO = BHI + 16384;
    static constexpr int STG = BLO + 16384;      // 96 KB / 64 KB
    static constexpr int STATS = 2 * STG;
    static constexpr int TOT = STATS + 16384;    // 208 KB / 144 KB
};

template <int TERMS, int KK>
__device__ __forceinline__ void load_stage256(uint32_t sbase,
                                              const __half* A, const __half* Al,
                                              const __half* B, const __half* Bl,
                                              int k0, int tid) {
#pragma unroll
    for (int it = 0; it < 8; it++) {
        int idx = tid + it * 256;
        int r = idx >> 3, c = idx & 7;
        uint32_t so = sw128((uint32_t)(r * 128 + c * 16));
        size_t go = (size_t)r * KK + k0 + c * 8;
        cp16(sbase + G2<TERMS>::AHI + so, A + go);
        if (TERMS == 3) cp16(sbase + G2<TERMS>::ALO + so, Al + go);
    }
#pragma unroll
    for (int it = 0; it < 4; it++) {
        int idx = tid + it * 256;
        int r = idx >> 3, c = idx & 7;
        uint32_t so = sw128((uint32_t)(r * 128 + c * 16));
        size_t go = (size_t)r * KK + k0 + c * 8;
        cp16(sbase + G2<TERMS>::BHI + so, B + go);
        cp16(sbase + G2<TERMS>::BLO + so, Bl + go);
    }
    asm volatile("cp.async.commit_group;" ::: "memory");
}

// ---------------------------------------------------------------------------
// Elementwise device bodies (stats fused, identical arithmetic to R10/11)
// ---------------------------------------------------------------------------
__device__ void lif_dev(int blk, int b0, const float4* __restrict__ h4,
                        const float* __restrict__ psum, const float* __restrict__ psq,
                        const float4* __restrict__ g4, const float4* __restrict__ be4,
                        uint2* __restrict__ spk4) {
    __shared__ float smean[256], srstd[256];
    int tid = threadIdx.x;
    int b = b0 + blk;
    {
        size_t row = (size_t)b * 256 + tid;
        float s = 0.f, q = 0.f;
#pragma unroll
        for (int p = 0; p < 8; p++) { s += psum[row * 8 + p]; q += psq[row * 8 + p]; }
        float m = s * (1.0f / Hsz);
        float var = fmaxf(q * (1.0f / Hsz) - m * m, 0.0f);
        smean[tid] = m;
        srstd[tid] = 1.0f / sqrtf(var + 1e-5f);
    }
    __syncthreads();

    const int C4 = Hsz / 4;   // 256, one j4 per thread
    int j = tid;
    float4 gg = g4[j], bb = be4[j];
    float v0 = 0.f, v1 = 0.f, v2 = 0.f, v3 = 0.f;
    size_t base = (size_t)b * Tsz * C4 + j;
#pragma unroll 4
    for (int t = 0; t < Tsz; t++) {
        float4 xi = h4[base + (size_t)t * C4];
        float m = smean[t], inv = srstd[t];
        float n0 = (xi.x - m) * inv * gg.x + bb.x;
        float n1 = (xi.y - m) * inv * gg.y + bb.y;
        float n2 = (xi.z - m) * inv * gg.z + bb.z;
        float n3 = (xi.w - m) * inv * gg.w + bb.w;
        v0 = v0 + (n0 - v0) * 0.5f;
        v1 = v1 + (n1 - v1) * 0.5f;
        v2 = v2 + (n2 - v2) * 0.5f;
        v3 = v3 + (n3 - v3) * 0.5f;
        float s0 = 0.f, s1 = 0.f, s2 = 0.f, s3 = 0.f;
        if (v0 >= 1.0f) { s0 = 1.0f; v0 = 0.f; }
        if (v1 >= 1.0f) { s1 = 1.0f; v1 = 0.f; }
        if (v2 >= 1.0f) { s2 = 1.0f; v2 = 0.f; }
        if (v3 >= 1.0f) { s3 = 1.0f; v3 = 0.f; }
        __half2 lo2 = __halves2half2(__float2half_rn(s0), __float2half_rn(s1));
        __half2 hi2 = __halves2half2(__float2half_rn(s2), __float2half_rn(s3));
        uint2 pack = { *(uint32_t*)&lo2, *(uint32_t*)&hi2 };
        spk4[base + (size_t)t * C4] = pack;
    }
}

__device__ void lifadd_dev(int blk, int b0, const float4* __restrict__ h4,
                           const float* __restrict__ psum, const float* __restrict__ psq,
                           const float4* __restrict__ g4, const float4* __restrict__ be4,
                           float* __restrict__ x, __half* __restrict__ xhi,
                           __half* __restrict__ xlo) {
    __shared__ float smean[512], srstd[512];
    int tid = threadIdx.x;
    int bpair = b0 + blk * 2;
    {
#pragma unroll
        for (int h = 0; h < 2; h++) {
            size_t row = (size_t)bpair * 256 + tid + h * 256;
            float s = 0.f, q = 0.f;
#pragma unroll
            for (int p = 0; p < 4; p++) { s += psum[row * 8 + p]; q += psq[row * 8 + p]; }
            float m = s * (1.0f / Esz);
            float var = fmaxf(q * (1.0f / Esz) - m * m, 0.0f);
            smean[tid + h * 256] = m;
            srstd[tid + h * 256] = 1.0f / sqrtf(var + 1e-5f);
        }
    }
    __syncthreads();

    const int C4 = Esz / 4;   // 128
    int bb8 = tid >> 7, j = tid & 127;
    int b = bpair + bb8;
    float4 gg = g4[j], bbv = be4[j];
    float v0 = 0.f, v1 = 0.f, v2 = 0.f, v3 = 0.f;
    size_t base = (size_t)b * Tsz * C4 + j;
#pragma unroll 4
    for (int t = 0; t < Tsz; t++) {
        float4 xi = h4[base + (size_t)t * C4];
        float m = smean[bb8 * 256 + t], inv = srstd[bb8 * 256 + t];
        float n0 = (xi.x - m) * inv * gg.x + bbv.x;
        float n1 = (xi.y - m) * inv * gg.y + bbv.y;
        float n2 = (xi.z - m) * inv * gg.z + bbv.z;
        float n3 = (xi.w - m) * inv * gg.w + bbv.w;
        v0 = v0 + (n0 - v0) * 0.5f;
        v1 = v1 + (n1 - v1) * 0.5f;
        v2 = v2 + (n2 - v2) * 0.5f;
        v3 = v3 + (n3 - v3) * 0.5f;
        size_t o = (size_t)b * Tsz * Esz + (size_t)t * Esz + j * 4;
#pragma unroll
        for (int cc = 0; cc < 4; cc++) {
            float* vp = (cc == 0) ? &v0 : (cc == 1) ? &v1 : (cc == 2) ? &v2 : &v3;
            if (*vp >= 1.0f) {
                *vp = 0.f;
                float xv = x[o + cc] + 1.0f;
                x[o + cc] = xv;
                __half hh = __float2half_rn(xv);
                xhi[o + cc] = hh;
                xlo[o + cc] = __float2half_rn(xv - __half2float(hh));
            }
        }
    }
}

// ---------------------------------------------------------------------------
// Mega kernel: blocks [0, ng) run the GEMM role; the rest run LK elementwise.
// LK: 0 none, 1 lif (H), 2 lifadd (E)
// ---------------------------------------------------------------------------
template <int TERMS, int TILES, int KK, int NTOT, int LK>
__global__ void __launch_bounds__(256, 1)
mega(int ng,
     const __half* __restrict__ Ahi, const __half* __restrict__ Alo,
     const __half* __restrict__ Bhi, const __half* __restrict__ Blo,
     const float* __restrict__ bias, float* __restrict__ C,
     float* __restrict__ psum, float* __restrict__ psq, int grow0,
     const float4* __restrict__ lh4, const float4* __restrict__ lg4,
     const float4* __restrict__ lb4, uint2* __restrict__ lspk4,
     float* __restrict__ lx, __half* __restrict__ lxhi, __half* __restrict__ lxlo,
     int lb0) {
    using GG = G2<TERMS>;
    int bid = blockIdx.x;

    if (bid >= ng) {
        if constexpr (LK == 1)
            lif_dev(bid - ng, lb0, lh4, psum, psq, lg4, lb4, lspk4);
        else if constexpr (LK == 2)
            lifadd_dev(bid - ng, lb0, lh4, psum, psq, lg4, lb4, lx, lxhi, lxlo);
        return;
    }

    constexpr int NGX = NTOT / (128 * TILES);
    int bxg = bid % NGX, by = bid / NGX;

    extern __shared__ char smc[];
    uint32_t sb = s2u(smc);
    float* ssum = (float*)(smc + GG::STATS);
    float* ssq  = (float*)(smc + GG::STATS + 8192);
    int tid = threadIdx.x;
    int wid = tid >> 5, lane = tid & 31;
    int warp_m = wid >> 1, warp_n = wid & 1;
    int row_in = lane & 7, grp = lane >> 3;

    constexpr int NC = KK / 64;
    constexpr int TC = TILES * NC;

    const __half* Ah = Ahi + (size_t)(grow0 + by * 256) * KK;
    const __half* Al = Alo + (size_t)(grow0 + by * 256) * KK;

    float acc[4][8][4] = {};
    uint32_t ahi[4][4], alo[4][4], bhi[8][2], blo[8][2];

    {
        const __half* Bh0 = Bhi + (size_t)(bxg * TILES * 128) * KK;
        const __half* Bl0 = Blo + (size_t)(bxg * TILES * 128) * KK;
        load_stage256<TERMS, KK>(sb, Ah, Al, Bh0, Bl0, 0, tid);
    }

    for (int g = 0; g < TC; g++) {
        int tile = g / NC, c = g % NC;
        asm volatile("cp.async.wait_group 0;" ::: "memory");
        __syncthreads();

        int g1 = g + 1;
        if (g1 < TC) {
            int t1 = g1 / NC, c1 = g1 % NC;
            const __half* Bh1 = Bhi + (size_t)((bxg * TILES + t1) * 128) * KK;
            const __half* Bl1 = Blo + (size_t)((bxg * TILES + t1) * 128) * KK;
            load_stage256<TERMS, KK>(sb + (g1 & 1) * GG::STG, Ah, Al, Bh1, Bl1, c1 * 64, tid);
        }

        uint32_t stg = sb + (g & 1) * GG::STG;
#pragma unroll
        for (int ks = 0; ks < 4; ks++) {
#pragma unroll
            for (int mf = 0; mf < 4; mf++) {
                int r = warp_m * 64 + mf * 16 + (grp & 1) * 8 + row_in;
                int kb = ks * 32 + (grp >> 1) * 16;
                uint32_t off = sw128((uint32_t)(r * 128 + kb));
                LDSM4(ahi[mf][0], ahi[mf][1], ahi[mf][2], ahi[mf][3], stg + GG::AHI + off);
                if (TERMS == 3)
                    LDSM4(alo[mf][0], alo[mf][1], alo[mf][2], alo[mf][3],
                          stg + GG::ALO + off);
            }
#pragma unroll
            for (int p = 0; p < 4; p++) {
                int r = warp_n * 64 + p * 16 + (grp >> 1) * 8 + row_in;
                int kb = ks * 32 + (grp & 1) * 16;
                uint32_t off = sw128((uint32_t)(r * 128 + kb));
                uint32_t t0, t1, t2, t3;
                LDSM4(t0, t1, t2, t3, stg + GG::BHI + off);
                bhi[2 * p][0] = t0; bhi[2 * p][1] = t1;
                bhi[2 * p + 1][0] = t2; bhi[2 * p + 1][1] = t3;
                LDSM4(t0, t1, t2, t3, stg + GG::BLO + off);
                blo[2 * p][0] = t0; blo[2 * p][1] = t1;
                blo[2 * p + 1][0] = t2; blo[2 * p + 1][1] = t3;
            }
            // per-acc order: hibhi -> hiblo -> lobhi (unchanged)
#pragma unroll
            for (int mf = 0; mf < 4; mf++)
#pragma unroll
                for (int nf = 0; nf < 8; nf++)
                    MMA16816(acc[mf][nf], ahi[mf], bhi[nf]);
#pragma unroll
            for (int mf = 0; mf < 4; mf++)
#pragma unroll
                for (int nf = 0; nf < 8; nf++)
                    MMA16816(acc[mf][nf], ahi[mf], blo[nf]);
            if (TERMS == 3) {
#pragma unroll
                for (int mf = 0; mf < 4; mf++)
#pragma unroll
                    for (int nf = 0; nf < 8; nf++)
                        MMA16816(acc[mf][nf], alo[mf], bhi[nf]);
            }
        }

        if (c == NC - 1) {
            int col_base = (bxg * TILES + tile) * 128 + warp_n * 64 + (lane & 3) * 2;
            int row_base = grow0 + by * 256 + warp_m * 64 + (lane >> 2);
            int contrib = warp_n * 4 + (lane & 3);
#pragma unroll
            for (int mf = 0; mf < 4; mf++) {
                float lsA = 0.f, lqA = 0.f, lsB = 0.f, lqB = 0.f;
#pragma unroll
                for (int nf = 0; nf < 8; nf++) {
                    int col = col_base + nf * 8;
                    float b0 = __ldg(bias + col), b1 = __ldg(bias + col + 1);
                    int r0 = row_base + mf * 16;
                    float2 v0 = { acc[mf][nf][0] + b0, acc[mf][nf][1] + b1 };
                    float2 v1 = { acc[mf][nf][2] + b0, acc[mf][nf][3] + b1 };
                    *(float2*)(C + (size_t)r0 * NTOT + col) = v0;
                    *(float2*)(C + (size_t)(r0 + 8) * NTOT + col) = v1;
                    lsA += v0.x + v0.y; lqA += v0.x * v0.x + v0.y * v0.y;
                    lsB += v1.x + v1.y; lqB += v1.x * v1.x + v1.y * v1.y;
                }
                int rA = warp_m * 64 + mf * 16 + (lane >> 2);
                ssum[rA * 8 + contrib] = lsA;
                ssq [rA * 8 + contrib] = lqA;
                ssum[(rA + 8) * 8 + contrib] = lsB;
                ssq [(rA + 8) * 8 + contrib] = lqB;
#pragma unroll
                for (int nf = 0; nf < 8; nf++)
#pragma unroll
                    for (int q = 0; q < 4; q++) acc[mf][nf][q] = 0.0f;
            }
            __syncthreads();
            {
                float s = 0.f, q = 0.f;
#pragma unroll
                for (int p = 0; p < 8; p++) { s += ssum[tid * 8 + p]; q += ssq[tid * 8 + p]; }
                int tcol = bxg * TILES + tile;
                size_t row = (size_t)(grow0 + by * 256 + tid);
                psum[row * 8 + tcol] = s;   // uniform stride 8
                psq [row * 8 + tcol] = q;
            }
            __syncthreads();
        }
    }
}

// ---------------------------------------------------------------------------
// Input projector, tiled (16 rows/block, W2 read once per block)
// ---------------------------------------------------------------------------
#define PR 16
__global__ void __launch_bounds__(256)
proj_kernel(const float* __restrict__ hist,
            const float* __restrict__ W1, const float* __restrict__ b1,
            const float* __restrict__ W2, const float* __restrict__ b2,
            float* __restrict__ out,
            __half* __restrict__ ohi, __half* __restrict__ olo) {
    __shared__ float hs[PR * INsz];
    __shared__ float hpT[HPsz][PR];
    int rb = blockIdx.x * PR;
    int tid = threadIdx.x;

    if (tid < PR * INsz) hs[tid] = hist[(size_t)rb * INsz + tid];
    __syncthreads();

#pragma unroll
    for (int i = 0; i < (PR * HPsz) / 256; i++) {
        int idx = tid + i * 256;
        int r = idx >> 6, cc = idx & 63;
        float a = b1[cc];
#pragma unroll
        for (int k = 0; k < INsz; k++) a += hs[r * INsz + k] * W1[k * HPsz + cc];
        hpT[cc][r] = 0.5f * a * (1.0f + erff(a * 0.70710678118654752440f));
    }
    __syncthreads();

    int c0 = tid * 2;
    float acc[PR][2];
    float bb0 = b2[c0], bb1 = b2[c0 + 1];
#pragma unroll
    for (int r = 0; r < PR; r++) { acc[r][0] = bb0; acc[r][1] = bb1; }

    for (int k = 0; k < HPsz; k++) {
        float2 w = *(const float2*)(W2 + (size_t)k * Esz + c0);
        float4 h0 = *(const float4*)&hpT[k][0];
        float4 h1 = *(const float4*)&hpT[k][4];
        float4 h2 = *(const float4*)&hpT[k][8];
        float4 h3 = *(const float4*)&hpT[k][12];
        float hk[PR] = { h0.x, h0.y, h0.z, h0.w, h1.x, h1.y, h1.z, h1.w,
                         h2.x, h2.y, h2.z, h2.w, h3.x, h3.y, h3.z, h3.w };
#pragma unroll
        for (int r = 0; r < PR; r++) {
            acc[r][0] += hk[r] * w.x;
            acc[r][1] += hk[r] * w.y;
        }
    }

#pragma unroll
    for (int r = 0; r < PR; r++) {
        size_t off = (size_t)(rb + r) * Esz + c0;
        float a0 = acc[r][0], a1 = acc[r][1];
        *(float2*)(out + off) = make_float2(a0, a1);
        __half h0 = __float2half_rn(a0), h1 = __float2half_rn(a1);
        *(__half2*)(ohi + off) = __halves2half2(h0, h1);
        *(__half2*)(olo + off) = __halves2half2(
            __float2half_rn(a0 - __half2float(h0)),
            __float2half_rn(a1 - __half2float(h1)));
    }
}

// Extract last timestep
__global__ void last_kernel(const float* __restrict__ x, float* __restrict__ out) {
    int i = blockIdx.x * blockDim.x + threadIdx.x;
    if (i < Bsz * Esz) {
        int b = i / Esz, e = i % Esz;
        out[i] = x[((size_t)b * Tsz + (Tsz - 1)) * Esz + e];
    }
}

// ---------------------------------------------------------------------------
extern "C" void kernel_launch(void* const* d_in, const int* in_sizes, int n_in,
                              void* d_out, int out_size) {
    const float* hist  = (const float*)d_in[0];
    const float* pW1   = (const float*)d_in[1];
    const float* pb1   = (const float*)d_in[2];
    const float* pW2   = (const float*)d_in[3];
    const float* pb2   = (const float*)d_in[4];
    const float* fc1_w = (const float*)d_in[5];
    const float* fc1_b = (const float*)d_in[6];
    const float* ln1_g = (const float*)d_in[7];
    const float* ln1_b = (const float*)d_in[8];
    const float* fc2_w = (const float*)d_in[9];
    const float* fc2_b = (const float*)d_in[10];
    const float* ln2_g = (const float*)d_in[11];
    const float* ln2_b = (const float*)d_in[12];

    float *x, *h1, *h2, *psum, *psq;
    __half *xhi, *xlo, *spk, *w1hi, *w1lo, *w2hi, *w2lo;
    cudaGetSymbolAddress((void**)&x,    g_x);
    cudaGetSymbolAddress((void**)&h1,   g_h1);
    cudaGetSymbolAddress((void**)&h2,   g_h2);
    cudaGetSymbolAddress((void**)&psum, g_psum);
    cudaGetSymbolAddress((void**)&psq,  g_psq);
    cudaGetSymbolAddress((void**)&xhi,  g_xhi);
    cudaGetSymbolAddress((void**)&xlo,  g_xlo);
    cudaGetSymbolAddress((void**)&spk,  g_spk);
    cudaGetSymbolAddress((void**)&w1hi, g_w1hi);
    cudaGetSymbolAddress((void**)&w1lo, g_w1lo);
    cudaGetSymbolAddress((void**)&w2hi, g_w2hi);
    cudaGetSymbolAddress((void**)&w2lo, g_w2lo);

    // Mega instantiations
    auto* m10 = mega<3, 2, Esz, Hsz, 0>;   // G1 only
    auto* m11 = mega<3, 2, Esz, Hsz, 1>;   // G1 + lif
    auto* m12 = mega<3, 2, Esz, Hsz, 2>;   // G1 + lifadd
    auto* m21 = mega<2, 1, Hsz, Esz, 1>;   // G2 + lif
    auto* m22 = mega<2, 1, Hsz, Esz, 2>;   // G2 + lifadd
    const int T1 = G2<3>::TOT;   // 212992
    const int T2 = G2<2>::TOT;   // 147456
    cudaFuncSetAttribute(m10, cudaFuncAttributeMaxDynamicSharedMemorySize, T1);
    cudaFuncSetAttribute(m11, cudaFuncAttributeMaxDynamicSharedMemorySize, T1);
    cudaFuncSetAttribute(m12, cudaFuncAttributeMaxDynamicSharedMemorySize, T1);
    cudaFuncSetAttribute(m21, cudaFuncAttributeMaxDynamicSharedMemorySize, T2);
    cudaFuncSetAttribute(m22, cudaFuncAttributeMaxDynamicSharedMemorySize, T2);

    split_w<<<dim3((Esz * Hsz + 255) / 256, Dsz), 256>>>(fc1_w, w1hi, w1lo, Esz, Hsz);
    split_w<<<dim3((Hsz * Esz + 255) / 256, Dsz), 256>>>(fc2_w, w2hi, w2lo, Hsz, Esz);

    proj_kernel<<<ROWS / PR, 256>>>(hist, pW1, pb1, pW2, pb2, x, xhi, xlo);

    const int NG = 512;        // gemm blocks per slice (both gemms: 4 x 128)
    const int NLIF = 128;      // lif blocks per slice (H)
    const int NLA = 64;        // lifadd blocks per slice (E)

    for (int d = 0; d < Dsz; d++) {
        size_t o1 = (size_t)d * Hsz * Esz;
        size_t o2 = (size_t)d * Esz * Hsz;
        const float* b1p = fc1_b + d * Hsz;
        const float* b2p = fc2_b + d * Esz;
        const float4* g1g = (const float4*)(ln1_g + d * Hsz);
        const float4* g1b = (const float4*)(ln1_b + d * Hsz);
        const float4* g2g = (const float4*)(ln2_g + d * Esz);
        const float4* g2b = (const float4*)(ln2_b + d * Esz);

        // stage 4d+0: G1(A,d)  [+ lifadd(B,d-1)]
        if (d == 0) {
            m10<<<NG, 256, T1>>>(NG, xhi, xlo, w1hi + o1, w1lo + o1, b1p, h1,
                                 psum, psq, 0,
                                 nullptr, nullptr, nullptr, nullptr,
                                 nullptr, nullptr, nullptr, 0);
        } else {
            const float4* pg = (const float4*)(ln2_g + (d - 1) * Esz);
            const float4* pb = (const float4*)(ln2_b + (d - 1) * Esz);
            m12<<<NG + NLA, 256, T1>>>(NG, xhi, xlo, w1hi + o1, w1lo + o1, b1p, h1,
                                       psum, psq, 0,
                                       (const float4*)h2, pg, pb, nullptr,
                                       x, xhi, xlo, 128);
        }
        // stage 4d+1: G1(B,d) + lif(A,d)
        m11<<<NG + NLIF, 256, T1>>>(NG, xhi, xlo, w1hi + o1, w1lo + o1, b1p, h1,
                                    psum, psq, HRWS,
                                    (const float4*)h1, g1g, g1b, (uint2*)spk,
                                    nullptr, nullptr, nullptr, 0);
        // stage 4d+2: G2(A,d) + lif(B,d)
        m21<<<NG + NLIF, 256, T2>>>(NG, spk, spk, w2hi + o2, w2lo + o2, b2p, h2,
                                    psum, psq, 0,
                                    (const float4*)h1, g1g, g1b, (uint2*)spk,
                                    nullptr, nullptr, nullptr, 128);
        // stage 4d+3: G2(B,d) + lifadd(A,d)
        m22<<<NG + NLA, 256, T2>>>(NG, spk, spk, w2hi + o2, w2lo + o2, b2p, h2,
                                   psum, psq, HRWS,
                                   (const float4*)h2, g2g, g2b, nullptr,
                                   x, xhi, xlo, 0);
    }
    // final: lifadd(B, 3) alone
    {
        size_t o2 = (size_t)3 * Esz * Hsz;
        m22<<<NLA, 256, T2>>>(0, spk, spk, w2hi + o2, w2lo + o2, fc2_b + 3 * Esz, h2,
                              psum, psq, HRWS,
                              (const float4*)h2, (const float4*)(ln2_g + 3 * Esz),
                              (const float4*)(ln2_b + 3 * Esz), nullptr,
                              x, xhi, xlo, 128);
    }

    last_kernel<<<(Bsz * Esz + 255) / 256, 256>>>(x, (float*)d_out);
}

// round 13
// speedup vs baseline: 1.1829x; 1.1829x over previous
#include <cuda_runtime.h>
#include <cuda_fp16.h>
#include <math.h>
#include <stdint.h>

// Problem dims
#define Bsz  256
#define Tsz  256
#define INsz 4
#define HPsz 64
#define Esz  512
#define Hsz  1024
#define Dsz  4
#define ROWS (Bsz * Tsz)   // 65536

// ---------------------------------------------------------------------------
// Scratch (device globals; no allocation allowed)
// ---------------------------------------------------------------------------
__device__ float  g_x  [(size_t)ROWS * Esz];
__device__ __half g_xhi[(size_t)ROWS * Esz];
__device__ __half g_xlo[(size_t)ROWS * Esz];
__device__ float  g_h1 [(size_t)ROWS * Hsz];
__device__ __half g_spk[(size_t)ROWS * Hsz];
__device__ float  g_h2 [(size_t)ROWS * Esz];
__device__ float  g_psum[(size_t)ROWS * 8];   // stride 8 for BOTH gemms
__device__ float  g_psq [(size_t)ROWS * 8];
__device__ __half g_w1hi[(size_t)Dsz * Hsz * Esz];
__device__ __half g_w1lo[(size_t)Dsz * Hsz * Esz];
__device__ __half g_w2hi[(size_t)Dsz * Esz * Hsz];
__device__ __half g_w2lo[(size_t)Dsz * Esz * Hsz];

// ---------------------------------------------------------------------------
// Helpers
// ---------------------------------------------------------------------------
__device__ __forceinline__ uint32_t sw128(uint32_t b) { return b ^ ((b >> 3) & 0x70); }

__device__ __forceinline__ uint32_t s2u(const void* p) {
    uint32_t a;
    asm("{ .reg .u64 t; cvta.to.shared.u64 t, %1; cvt.u32.u64 %0, t; }" : "=r"(a) : "l"(p));
    return a;
}

__device__ __forceinline__ void cp16(uint32_t saddr, const void* g) {
    asm volatile("cp.async.cg.shared.global [%0], [%1], 16;" :: "r"(saddr), "l"(g));
}

#define LDSM4(r0, r1, r2, r3, addr)                                           \
    asm volatile("ldmatrix.sync.aligned.m8n8.x4.shared.b16 {%0,%1,%2,%3}, [%4];" \
                 : "=r"(r0), "=r"(r1), "=r"(r2), "=r"(r3) : "r"(addr))

#define MMA16816(d, a, b)                                                     \
    asm volatile(                                                             \
        "mma.sync.aligned.m16n8k16.row.col.f32.f16.f16.f32 "                  \
        "{%0,%1,%2,%3},{%4,%5,%6,%7},{%8,%9},{%0,%1,%2,%3};"                  \
        : "+f"((d)[0]), "+f"((d)[1]), "+f"((d)[2]), "+f"((d)[3])              \
        : "r"((a)[0]), "r"((a)[1]), "r"((a)[2]), "r"((a)[3]),                 \
          "r"((b)[0]), "r"((b)[1]))

// ---------------------------------------------------------------------------
// Split+transpose weights
// ---------------------------------------------------------------------------
__global__ void split_w(const float* __restrict__ W, __half* __restrict__ hi,
                        __half* __restrict__ lo, int K, int N) {
    int idx = blockIdx.x * blockDim.x + threadIdx.x;
    if (idx >= K * N) return;
    size_t lofs = (size_t)blockIdx.y * K * N;
    int k = idx / N, n = idx % N;
    float w = W[lofs + idx];
    __half h = __float2half_rn(w);
    hi[lofs + (size_t)n * K + k] = h;
    lo[lofs + (size_t)n * K + k] = __float2half_rn(w - __half2float(h));
}

// ---------------------------------------------------------------------------
// GEMM: C = Ahi@Bhi^T + Ahi@Blo^T (+ Alo@Bhi^T) + bias; epilogue emits
// per-tile LN partials (stride-8). CTA 256x128, warp 64x64, BK=64, 2-stage.
// ---------------------------------------------------------------------------
template <int TERMS> struct G2 {
    static constexpr int AHI = 0;
    static constexpr int ALO = 32768;
    static constexpr int BHI = (TERMS == 3) ? 65536 : 32768;
    static constexpr int BLO = BHI + 16384;
    static constexpr int STG = BLO + 16384;      // 96 KB / 64 KB
    static constexpr int STATS = 2 * STG;
    static constexpr int TOT = STATS + 16384;    // 208 KB / 144 KB
};

template <int TERMS, int KK>
__device__ __forceinline__ void load_stage256(uint32_t sbase,
                                              const __half* A, const __half* Al,
                                              const __half* B, const __half* Bl,
                                              int k0, int tid) {
#pragma unroll
    for (int it = 0; it < 8; it++) {
        int idx = tid + it * 256;
        int r = idx >> 3, c = idx & 7;
        uint32_t so = sw128((uint32_t)(r * 128 + c * 16));
        size_t go = (size_t)r * KK + k0 + c * 8;
        cp16(sbase + G2<TERMS>::AHI + so, A + go);
        if (TERMS == 3) cp16(sbase + G2<TERMS>::ALO + so, Al + go);
    }
#pragma unroll
    for (int it = 0; it < 4; it++) {
        int idx = tid + it * 256;
        int r = idx >> 3, c = idx & 7;
        uint32_t so = sw128((uint32_t)(r * 128 + c * 16));
        size_t go = (size_t)r * KK + k0 + c * 8;
        cp16(sbase + G2<TERMS>::BHI + so, B + go);
        cp16(sbase + G2<TERMS>::BLO + so, Bl + go);
    }
    asm volatile("cp.async.commit_group;" ::: "memory");
}

template <int TERMS, int TILES, int KK, int NTOT>
__global__ void __launch_bounds__(256, 1)
gemm_hs256(const __half* __restrict__ Ahi, const __half* __restrict__ Alo,
           const __half* __restrict__ Bhi, const __half* __restrict__ Blo,
           const float* __restrict__ bias, float* __restrict__ C,
           float* __restrict__ psum, float* __restrict__ psq) {
    using GG = G2<TERMS>;
    extern __shared__ char smc[];
    uint32_t sb = s2u(smc);
    float* ssum = (float*)(smc + GG::STATS);
    float* ssq  = (float*)(smc + GG::STATS + 8192);
    int tid = threadIdx.x;
    int wid = tid >> 5, lane = tid & 31;
    int warp_m = wid >> 1, warp_n = wid & 1;
    int bxg = blockIdx.x, by = blockIdx.y;
    int row_in = lane & 7, grp = lane >> 3;

    constexpr int NC = KK / 64;
    constexpr int TC = TILES * NC;

    const __half* Ah = Ahi + (size_t)(by * 256) * KK;
    const __half* Al = Alo + (size_t)(by * 256) * KK;

    float acc[4][8][4] = {};
    uint32_t ahi[4][4], alo[4][4], bhi[8][2], blo[8][2];

    {
        const __half* Bh0 = Bhi + (size_t)(bxg * TILES * 128) * KK;
        const __half* Bl0 = Blo + (size_t)(bxg * TILES * 128) * KK;
        load_stage256<TERMS, KK>(sb, Ah, Al, Bh0, Bl0, 0, tid);
    }

    for (int g = 0; g < TC; g++) {
        int tile = g / NC, c = g % NC;
        asm volatile("cp.async.wait_group 0;" ::: "memory");
        __syncthreads();

        int g1 = g + 1;
        if (g1 < TC) {
            int t1 = g1 / NC, c1 = g1 % NC;
            const __half* Bh1 = Bhi + (size_t)((bxg * TILES + t1) * 128) * KK;
            const __half* Bl1 = Blo + (size_t)((bxg * TILES + t1) * 128) * KK;
            load_stage256<TERMS, KK>(sb + (g1 & 1) * GG::STG, Ah, Al, Bh1, Bl1, c1 * 64, tid);
        }

        uint32_t stg = sb + (g & 1) * GG::STG;
#pragma unroll
        for (int ks = 0; ks < 4; ks++) {
#pragma unroll
            for (int mf = 0; mf < 4; mf++) {
                int r = warp_m * 64 + mf * 16 + (grp & 1) * 8 + row_in;
                int kb = ks * 32 + (grp >> 1) * 16;
                uint32_t off = sw128((uint32_t)(r * 128 + kb));
                LDSM4(ahi[mf][0], ahi[mf][1], ahi[mf][2], ahi[mf][3], stg + GG::AHI + off);
                if (TERMS == 3)
                    LDSM4(alo[mf][0], alo[mf][1], alo[mf][2], alo[mf][3],
                          stg + GG::ALO + off);
            }
#pragma unroll
            for (int p = 0; p < 4; p++) {
                int r = warp_n * 64 + p * 16 + (grp >> 1) * 8 + row_in;
                int kb = ks * 32 + (grp & 1) * 16;
                uint32_t off = sw128((uint32_t)(r * 128 + kb));
                uint32_t t0, t1, t2, t3;
                LDSM4(t0, t1, t2, t3, stg + GG::BHI + off);
                bhi[2 * p][0] = t0; bhi[2 * p][1] = t1;
                bhi[2 * p + 1][0] = t2; bhi[2 * p + 1][1] = t3;
                LDSM4(t0, t1, t2, t3, stg + GG::BLO + off);
                blo[2 * p][0] = t0; blo[2 * p][1] = t1;
                blo[2 * p + 1][0] = t2; blo[2 * p + 1][1] = t3;
            }
            // per-acc order: hibhi -> hiblo -> lobhi (unchanged)
#pragma unroll
            for (int mf = 0; mf < 4; mf++)
#pragma unroll
                for (int nf = 0; nf < 8; nf++)
                    MMA16816(acc[mf][nf], ahi[mf], bhi[nf]);
#pragma unroll
            for (int mf = 0; mf < 4; mf++)
#pragma unroll
                for (int nf = 0; nf < 8; nf++)
                    MMA16816(acc[mf][nf], ahi[mf], blo[nf]);
            if (TERMS == 3) {
#pragma unroll
                for (int mf = 0; mf < 4; mf++)
#pragma unroll
                    for (int nf = 0; nf < 8; nf++)
                        MMA16816(acc[mf][nf], alo[mf], bhi[nf]);
            }
        }

        if (c == NC - 1) {
            int col_base = (bxg * TILES + tile) * 128 + warp_n * 64 + (lane & 3) * 2;
            int row_base = by * 256 + warp_m * 64 + (lane >> 2);
            int contrib = warp_n * 4 + (lane & 3);
#pragma unroll
            for (int mf = 0; mf < 4; mf++) {
                float lsA = 0.f, lqA = 0.f, lsB = 0.f, lqB = 0.f;
#pragma unroll
                for (int nf = 0; nf < 8; nf++) {
                    int col = col_base + nf * 8;
                    float b0 = __ldg(bias + col), b1 = __ldg(bias + col + 1);
                    int r0 = row_base + mf * 16;
                    float2 v0 = { acc[mf][nf][0] + b0, acc[mf][nf][1] + b1 };
                    float2 v1 = { acc[mf][nf][2] + b0, acc[mf][nf][3] + b1 };
                    *(float2*)(C + (size_t)r0 * NTOT + col) = v0;
                    *(float2*)(C + (size_t)(r0 + 8) * NTOT + col) = v1;
                    lsA += v0.x + v0.y; lqA += v0.x * v0.x + v0.y * v0.y;
                    lsB += v1.x + v1.y; lqB += v1.x * v1.x + v1.y * v1.y;
                }
                int rA = warp_m * 64 + mf * 16 + (lane >> 2);
                ssum[rA * 8 + contrib] = lsA;
                ssq [rA * 8 + contrib] = lqA;
                ssum[(rA + 8) * 8 + contrib] = lsB;
                ssq [(rA + 8) * 8 + contrib] = lqB;
#pragma unroll
                for (int nf = 0; nf < 8; nf++)
#pragma unroll
                    for (int q = 0; q < 4; q++) acc[mf][nf][q] = 0.0f;
            }
            __syncthreads();
            {
                float s = 0.f, q = 0.f;
#pragma unroll
                for (int p = 0; p < 8; p++) { s += ssum[tid * 8 + p]; q += ssq[tid * 8 + p]; }
                int tcol = bxg * TILES + tile;
                size_t row = (size_t)(by * 256 + tid);
                psum[row * 8 + tcol] = s;   // uniform stride 8
                psq [row * 8 + tcol] = q;
            }
            __syncthreads();
        }
    }
}

// ---------------------------------------------------------------------------
// Fused stats + LIF (validated bit-exact in Round 12).
// One block per batch; stats_finish arithmetic inlined; smem-cached mean/rstd.
// ---------------------------------------------------------------------------
__global__ void __launch_bounds__(256)
lif_fused(const float4* __restrict__ h4,
          const float* __restrict__ psum, const float* __restrict__ psq,
          const float4* __restrict__ g4, const float4* __restrict__ be4,
          uint2* __restrict__ spk4) {
    __shared__ float smean[256], srstd[256];
    int tid = threadIdx.x;
    int b = blockIdx.x;
    {
        size_t row = (size_t)b * 256 + tid;
        float s = 0.f, q = 0.f;
#pragma unroll
        for (int p = 0; p < 8; p++) { s += psum[row * 8 + p]; q += psq[row * 8 + p]; }
        float m = s * (1.0f / Hsz);
        float var = fmaxf(q * (1.0f / Hsz) - m * m, 0.0f);
        smean[tid] = m;
        srstd[tid] = 1.0f / sqrtf(var + 1e-5f);
    }
    __syncthreads();

    const int C4 = Hsz / 4;   // 256, one float4 per thread
    int j = tid;
    float4 gg = g4[j], bb = be4[j];
    float v0 = 0.f, v1 = 0.f, v2 = 0.f, v3 = 0.f;
    size_t base = (size_t)b * Tsz * C4 + j;
#pragma unroll 4
    for (int t = 0; t < Tsz; t++) {
        float4 xi = h4[base + (size_t)t * C4];
        float m = smean[t], inv = srstd[t];
        float n0 = (xi.x - m) * inv * gg.x + bb.x;
        float n1 = (xi.y - m) * inv * gg.y + bb.y;
        float n2 = (xi.z - m) * inv * gg.z + bb.z;
        float n3 = (xi.w - m) * inv * gg.w + bb.w;
        v0 = v0 + (n0 - v0) * 0.5f;
        v1 = v1 + (n1 - v1) * 0.5f;
        v2 = v2 + (n2 - v2) * 0.5f;
        v3 = v3 + (n3 - v3) * 0.5f;
        float s0 = 0.f, s1 = 0.f, s2 = 0.f, s3 = 0.f;
        if (v0 >= 1.0f) { s0 = 1.0f; v0 = 0.f; }
        if (v1 >= 1.0f) { s1 = 1.0f; v1 = 0.f; }
        if (v2 >= 1.0f) { s2 = 1.0f; v2 = 0.f; }
        if (v3 >= 1.0f) { s3 = 1.0f; v3 = 0.f; }
        __half2 lo2 = __halves2half2(__float2half_rn(s0), __float2half_rn(s1));
        __half2 hi2 = __halves2half2(__float2half_rn(s2), __float2half_rn(s3));
        uint2 pack = { *(uint32_t*)&lo2, *(uint32_t*)&hi2 };
        spk4[base + (size_t)t * C4] = pack;
    }
}

// Fused stats + LIF + residual add + sparse split refresh (validated in R12).
// One block per 2 batches (256 threads = 2 x 128 float4 lanes).
__global__ void __launch_bounds__(256)
lifadd_fused(const float4* __restrict__ h4,
             const float* __restrict__ psum, const float* __restrict__ psq,
             const float4* __restrict__ g4, const float4* __restrict__ be4,
             float* __restrict__ x, __half* __restrict__ xhi,
             __half* __restrict__ xlo) {
    __shared__ float smean[512], srstd[512];
    int tid = threadIdx.x;
    int bpair = blockIdx.x * 2;
    {
#pragma unroll
        for (int h = 0; h < 2; h++) {
            size_t row = (size_t)bpair * 256 + tid + h * 256;
            float s = 0.f, q = 0.f;
#pragma unroll
            for (int p = 0; p < 4; p++) { s += psum[row * 8 + p]; q += psq[row * 8 + p]; }
            float m = s * (1.0f / Esz);
            float var = fmaxf(q * (1.0f / Esz) - m * m, 0.0f);
            smean[tid + h * 256] = m;
            srstd[tid + h * 256] = 1.0f / sqrtf(var + 1e-5f);
        }
    }
    __syncthreads();

    const int C4 = Esz / 4;   // 128
    int bb8 = tid >> 7, j = tid & 127;
    int b = bpair + bb8;
    float4 gg = g4[j], bbv = be4[j];
    float v0 = 0.f, v1 = 0.f, v2 = 0.f, v3 = 0.f;
    size_t base = (size_t)b * Tsz * C4 + j;
#pragma unroll 4
    for (int t = 0; t < Tsz; t++) {
        float4 xi = h4[base + (size_t)t * C4];
        float m = smean[bb8 * 256 + t], inv = srstd[bb8 * 256 + t];
        float n0 = (xi.x - m) * inv * gg.x + bbv.x;
        float n1 = (xi.y - m) * inv * gg.y + bbv.y;
        float n2 = (xi.z - m) * inv * gg.z + bbv.z;
        float n3 = (xi.w - m) * inv * gg.w + bbv.w;
        v0 = v0 + (n0 - v0) * 0.5f;
        v1 = v1 + (n1 - v1) * 0.5f;
        v2 = v2 + (n2 - v2) * 0.5f;
        v3 = v3 + (n3 - v3) * 0.5f;
        size_t o = (size_t)b * Tsz * Esz + (size_t)t * Esz + j * 4;
#pragma unroll
        for (int cc = 0; cc < 4; cc++) {
            float* vp = (cc == 0) ? &v0 : (cc == 1) ? &v1 : (cc == 2) ? &v2 : &v3;
            if (*vp >= 1.0f) {
                *vp = 0.f;
                float xv = x[o + cc] + 1.0f;
                x[o + cc] = xv;
                __half hh = __float2half_rn(xv);
                xhi[o + cc] = hh;
                xlo[o + cc] = __float2half_rn(xv - __half2float(hh));
            }
        }
    }
}

// ---------------------------------------------------------------------------
// Input projector, tiled (16 rows/block, W2 read once per block)
// ---------------------------------------------------------------------------
#define PR 16
__global__ void __launch_bounds__(256)
proj_kernel(const float* __restrict__ hist,
            const float* __restrict__ W1, const float* __restrict__ b1,
            const float* __restrict__ W2, const float* __restrict__ b2,
            float* __restrict__ out,
            __half* __restrict__ ohi, __half* __restrict__ olo) {
    __shared__ float hs[PR * INsz];
    __shared__ float hpT[HPsz][PR];
    int rb = blockIdx.x * PR;
    int tid = threadIdx.x;

    if (tid < PR * INsz) hs[tid] = hist[(size_t)rb * INsz + tid];
    __syncthreads();

#pragma unroll
    for (int i = 0; i < (PR * HPsz) / 256; i++) {
        int idx = tid + i * 256;
        int r = idx >> 6, cc = idx & 63;
        float a = b1[cc];
#pragma unroll
        for (int k = 0; k < INsz; k++) a += hs[r * INsz + k] * W1[k * HPsz + cc];
        hpT[cc][r] = 0.5f * a * (1.0f + erff(a * 0.70710678118654752440f));
    }
    __syncthreads();

    int c0 = tid * 2;
    float acc[PR][2];
    float bb0 = b2[c0], bb1 = b2[c0 + 1];
#pragma unroll
    for (int r = 0; r < PR; r++) { acc[r][0] = bb0; acc[r][1] = bb1; }

    for (int k = 0; k < HPsz; k++) {
        float2 w = *(const float2*)(W2 + (size_t)k * Esz + c0);
        float4 h0 = *(const float4*)&hpT[k][0];
        float4 h1 = *(const float4*)&hpT[k][4];
        float4 h2 = *(const float4*)&hpT[k][8];
        float4 h3 = *(const float4*)&hpT[k][12];
        float hk[PR] = { h0.x, h0.y, h0.z, h0.w, h1.x, h1.y, h1.z, h1.w,
                         h2.x, h2.y, h2.z, h2.w, h3.x, h3.y, h3.z, h3.w };
#pragma unroll
        for (int r = 0; r < PR; r++) {
            acc[r][0] += hk[r] * w.x;
            acc[r][1] += hk[r] * w.y;
        }
    }

#pragma unroll
    for (int r = 0; r < PR; r++) {
        size_t off = (size_t)(rb + r) * Esz + c0;
        float a0 = acc[r][0], a1 = acc[r][1];
        *(float2*)(out + off) = make_float2(a0, a1);
        __half h0 = __float2half_rn(a0), h1 = __float2half_rn(a1);
        *(__half2*)(ohi + off) = __halves2half2(h0, h1);
        *(__half2*)(olo + off) = __halves2half2(
            __float2half_rn(a0 - __half2float(h0)),
            __float2half_rn(a1 - __half2float(h1)));
    }
}

// Extract last timestep
__global__ void last_kernel(const float* __restrict__ x, float* __restrict__ out) {
    int i = blockIdx.x * blockDim.x + threadIdx.x;
    if (i < Bsz * Esz) {
        int b = i / Esz, e = i % Esz;
        out[i] = x[((size_t)b * Tsz + (Tsz - 1)) * Esz + e];
    }
}

// ---------------------------------------------------------------------------
extern "C" void kernel_launch(void* const* d_in, const int* in_sizes, int n_in,
                              void* d_out, int out_size) {
    const float* hist  = (const float*)d_in[0];
    const float* pW1   = (const float*)d_in[1];
    const float* pb1   = (const float*)d_in[2];
    const float* pW2   = (const float*)d_in[3];
    const float* pb2   = (const float*)d_in[4];
    const float* fc1_w = (const float*)d_in[5];
    const float* fc1_b = (const float*)d_in[6];
    const float* ln1_g = (const float*)d_in[7];
    const float* ln1_b = (const float*)d_in[8];
    const float* fc2_w = (const float*)d_in[9];
    const float* fc2_b = (const float*)d_in[10];
    const float* ln2_g = (const float*)d_in[11];
    const float* ln2_b = (const float*)d_in[12];

    float *x, *h1, *h2, *psum, *psq;
    __half *xhi, *xlo, *spk, *w1hi, *w1lo, *w2hi, *w2lo;
    cudaGetSymbolAddress((void**)&x,    g_x);
    cudaGetSymbolAddress((void**)&h1,   g_h1);
    cudaGetSymbolAddress((void**)&h2,   g_h2);
    cudaGetSymbolAddress((void**)&psum, g_psum);
    cudaGetSymbolAddress((void**)&psq,  g_psq);
    cudaGetSymbolAddress((void**)&xhi,  g_xhi);
    cudaGetSymbolAddress((void**)&xlo,  g_xlo);
    cudaGetSymbolAddress((void**)&spk,  g_spk);
    cudaGetSymbolAddress((void**)&w1hi, g_w1hi);
    cudaGetSymbolAddress((void**)&w1lo, g_w1lo);
    cudaGetSymbolAddress((void**)&w2hi, g_w2hi);
    cudaGetSymbolAddress((void**)&w2lo, g_w2lo);

    auto* gk1 = gemm_hs256<3, 2, Esz, Hsz>;   // GEMM1: 2 N-tiles/CTA
    auto* gk2 = gemm_hs256<2, 1, Hsz, Esz>;   // GEMM2: 1 N-tile/CTA
    cudaFuncSetAttribute(gk1, cudaFuncAttributeMaxDynamicSharedMemorySize, G2<3>::TOT);
    cudaFuncSetAttribute(gk2, cudaFuncAttributeMaxDynamicSharedMemorySize, G2<2>::TOT);

    split_w<<<dim3((Esz * Hsz + 255) / 256, Dsz), 256>>>(fc1_w, w1hi, w1lo, Esz, Hsz);
    split_w<<<dim3((Hsz * Esz + 255) / 256, Dsz), 256>>>(fc2_w, w2hi, w2lo, Hsz, Esz);

    proj_kernel<<<ROWS / PR, 256>>>(hist, pW1, pb1, pW2, pb2, x, xhi, xlo);

    for (int d = 0; d < Dsz; d++) {
        size_t o1 = (size_t)d * Hsz * Esz;
        size_t o2 = (size_t)d * Esz * Hsz;

        gk1<<<dim3(Hsz / 128 / 2, ROWS / 256), 256, G2<3>::TOT>>>(
            xhi, xlo, w1hi + o1, w1lo + o1, fc1_b + d * Hsz, h1, psum, psq);
        lif_fused<<<Bsz, 256>>>(
            (const float4*)h1, psum, psq, (const float4*)(ln1_g + d * Hsz),
            (const float4*)(ln1_b + d * Hsz), (uint2*)spk);

        gk2<<<dim3(Esz / 128, ROWS / 256), 256, G2<2>::TOT>>>(
            spk, spk, w2hi + o2, w2lo + o2, fc2_b + d * Esz, h2, psum, psq);
        lifadd_fused<<<Bsz / 2, 256>>>(
            (const float4*)h2, psum, psq, (const float4*)(ln2_g + d * Esz),
            (const float4*)(ln2_b + d * Esz), x, xhi, xlo);
    }

    last_kernel<<<(Bsz * Esz + 255) / 256, 256>>>(x, (float*)d_out);
}

// round 14
// speedup vs baseline: 1.2856x; 1.0868x over previous
#include <cuda_runtime.h>
#include <cuda_fp16.h>
#include <math.h>
#include <stdint.h>

// Problem dims
#define Bsz  256
#define Tsz  256
#define INsz 4
#define HPsz 64
#define Esz  512
#define Hsz  1024
#define Dsz  4
#define ROWS (Bsz * Tsz)   // 65536

// ---------------------------------------------------------------------------
// Scratch (device globals; no allocation allowed)
// ---------------------------------------------------------------------------
__device__ float  g_x  [(size_t)ROWS * Esz];
__device__ __half g_xhi[(size_t)ROWS * Esz];
__device__ __half g_xlo[(size_t)ROWS * Esz];
__device__ float  g_h1 [(size_t)ROWS * Hsz];
__device__ __half g_spk[(size_t)ROWS * Hsz];
__device__ float  g_h2 [(size_t)ROWS * Esz];
__device__ float  g_psum[(size_t)ROWS * 8];   // stride 8 for BOTH gemms
__device__ float  g_psq [(size_t)ROWS * 8];
__device__ __half g_w1hi[(size_t)Dsz * Hsz * Esz];
__device__ __half g_w1lo[(size_t)Dsz * Hsz * Esz];
__device__ __half g_w2hi[(size_t)Dsz * Esz * Hsz];
__device__ __half g_w2lo[(size_t)Dsz * Esz * Hsz];

// ---------------------------------------------------------------------------
// Helpers
// ---------------------------------------------------------------------------
__device__ __forceinline__ uint32_t sw128(uint32_t b) { return b ^ ((b >> 3) & 0x70); }

__device__ __forceinline__ uint32_t s2u(const void* p) {
    uint32_t a;
    asm("{ .reg .u64 t; cvta.to.shared.u64 t, %1; cvt.u32.u64 %0, t; }" : "=r"(a) : "l"(p));
    return a;
}

__device__ __forceinline__ void cp16(uint32_t saddr, const void* g) {
    asm volatile("cp.async.cg.shared.global [%0], [%1], 16;" :: "r"(saddr), "l"(g));
}

#define LDSM4(r0, r1, r2, r3, addr)                                           \
    asm volatile("ldmatrix.sync.aligned.m8n8.x4.shared.b16 {%0,%1,%2,%3}, [%4];" \
                 : "=r"(r0), "=r"(r1), "=r"(r2), "=r"(r3) : "r"(addr))

#define MMA16816(d, a, b)                                                     \
    asm volatile(                                                             \
        "mma.sync.aligned.m16n8k16.row.col.f32.f16.f16.f32 "                  \
        "{%0,%1,%2,%3},{%4,%5,%6,%7},{%8,%9},{%0,%1,%2,%3};"                  \
        : "+f"((d)[0]), "+f"((d)[1]), "+f"((d)[2]), "+f"((d)[3])              \
        : "r"((a)[0]), "r"((a)[1]), "r"((a)[2]), "r"((a)[3]),                 \
          "r"((b)[0]), "r"((b)[1]))

// ---------------------------------------------------------------------------
// Split+transpose weights
// ---------------------------------------------------------------------------
__global__ void split_w(const float* __restrict__ W, __half* __restrict__ hi,
                        __half* __restrict__ lo, int K, int N) {
    int idx = blockIdx.x * blockDim.x + threadIdx.x;
    if (idx >= K * N) return;
    size_t lofs = (size_t)blockIdx.y * K * N;
    int k = idx / N, n = idx % N;
    float w = W[lofs + idx];
    __half h = __float2half_rn(w);
    hi[lofs + (size_t)n * K + k] = h;
    lo[lofs + (size_t)n * K + k] = __float2half_rn(w - __half2float(h));
}

// ---------------------------------------------------------------------------
// GEMM: C = Ahi@Bhi^T + Ahi@Blo^T (+ Alo@Bhi^T) + bias; epilogue emits
// per-tile LN partials (stride-8). CTA 256x128, warp 64x64, BK=64, 2-stage.
// ---------------------------------------------------------------------------
template <int TERMS> struct G2 {
    static constexpr int AHI = 0;
    static constexpr int ALO = 32768;
    static constexpr int BHI = (TERMS == 3) ? 65536 : 32768;
    static constexpr int BLO = BHI + 16384;
    static constexpr int STG = BLO + 16384;      // 96 KB / 64 KB
    static constexpr int STATS = 2 * STG;
    static constexpr int TOT = STATS + 16384;    // 208 KB / 144 KB
};

template <int TERMS, int KK>
__device__ __forceinline__ void load_stage256(uint32_t sbase,
                                              const __half* A, const __half* Al,
                                              const __half* B, const __half* Bl,
                                              int k0, int tid) {
#pragma unroll
    for (int it = 0; it < 8; it++) {
        int idx = tid + it * 256;
        int r = idx >> 3, c = idx & 7;
        uint32_t so = sw128((uint32_t)(r * 128 + c * 16));
        size_t go = (size_t)r * KK + k0 + c * 8;
        cp16(sbase + G2<TERMS>::AHI + so, A + go);
        if (TERMS == 3) cp16(sbase + G2<TERMS>::ALO + so, Al + go);
    }
#pragma unroll
    for (int it = 0; it < 4; it++) {
        int idx = tid + it * 256;
        int r = idx >> 3, c = idx & 7;
        uint32_t so = sw128((uint32_t)(r * 128 + c * 16));
        size_t go = (size_t)r * KK + k0 + c * 8;
        cp16(sbase + G2<TERMS>::BHI + so, B + go);
        cp16(sbase + G2<TERMS>::BLO + so, Bl + go);
    }
    asm volatile("cp.async.commit_group;" ::: "memory");
}

template <int TERMS, int TILES, int KK, int NTOT>
__global__ void __launch_bounds__(256, 1)
gemm_hs256(const __half* __restrict__ Ahi, const __half* __restrict__ Alo,
           const __half* __restrict__ Bhi, const __half* __restrict__ Blo,
           const float* __restrict__ bias, float* __restrict__ C,
           float* __restrict__ psum, float* __restrict__ psq) {
    using GG = G2<TERMS>;
    extern __shared__ char smc[];
    uint32_t sb = s2u(smc);
    float* ssum = (float*)(smc + GG::STATS);
    float* ssq  = (float*)(smc + GG::STATS + 8192);
    int tid = threadIdx.x;
    int wid = tid >> 5, lane = tid & 31;
    int warp_m = wid >> 1, warp_n = wid & 1;
    int bxg = blockIdx.x, by = blockIdx.y;
    int row_in = lane & 7, grp = lane >> 3;

    constexpr int NC = KK / 64;
    constexpr int TC = TILES * NC;

    const __half* Ah = Ahi + (size_t)(by * 256) * KK;
    const __half* Al = Alo + (size_t)(by * 256) * KK;

    float acc[4][8][4] = {};
    uint32_t ahi[4][4], alo[4][4], bhi[8][2], blo[8][2];

    {
        const __half* Bh0 = Bhi + (size_t)(bxg * TILES * 128) * KK;
        const __half* Bl0 = Blo + (size_t)(bxg * TILES * 128) * KK;
        load_stage256<TERMS, KK>(sb, Ah, Al, Bh0, Bl0, 0, tid);
    }

    for (int g = 0; g < TC; g++) {
        int tile = g / NC, c = g % NC;
        asm volatile("cp.async.wait_group 0;" ::: "memory");
        __syncthreads();

        int g1 = g + 1;
        if (g1 < TC) {
            int t1 = g1 / NC, c1 = g1 % NC;
            const __half* Bh1 = Bhi + (size_t)((bxg * TILES + t1) * 128) * KK;
            const __half* Bl1 = Blo + (size_t)((bxg * TILES + t1) * 128) * KK;
            load_stage256<TERMS, KK>(sb + (g1 & 1) * GG::STG, Ah, Al, Bh1, Bl1, c1 * 64, tid);
        }

        uint32_t stg = sb + (g & 1) * GG::STG;
#pragma unroll
        for (int ks = 0; ks < 4; ks++) {
#pragma unroll
            for (int mf = 0; mf < 4; mf++) {
                int r = warp_m * 64 + mf * 16 + (grp & 1) * 8 + row_in;
                int kb = ks * 32 + (grp >> 1) * 16;
                uint32_t off = sw128((uint32_t)(r * 128 + kb));
                LDSM4(ahi[mf][0], ahi[mf][1], ahi[mf][2], ahi[mf][3], stg + GG::AHI + off);
                if (TERMS == 3)
                    LDSM4(alo[mf][0], alo[mf][1], alo[mf][2], alo[mf][3],
                          stg + GG::ALO + off);
            }
#pragma unroll
            for (int p = 0; p < 4; p++) {
                int r = warp_n * 64 + p * 16 + (grp >> 1) * 8 + row_in;
                int kb = ks * 32 + (grp & 1) * 16;
                uint32_t off = sw128((uint32_t)(r * 128 + kb));
                uint32_t t0, t1, t2, t3;
                LDSM4(t0, t1, t2, t3, stg + GG::BHI + off);
                bhi[2 * p][0] = t0; bhi[2 * p][1] = t1;
                bhi[2 * p + 1][0] = t2; bhi[2 * p + 1][1] = t3;
                LDSM4(t0, t1, t2, t3, stg + GG::BLO + off);
                blo[2 * p][0] = t0; blo[2 * p][1] = t1;
                blo[2 * p + 1][0] = t2; blo[2 * p + 1][1] = t3;
            }
            // per-acc order: hibhi -> hiblo -> lobhi (unchanged)
#pragma unroll
            for (int mf = 0; mf < 4; mf++)
#pragma unroll
                for (int nf = 0; nf < 8; nf++)
                    MMA16816(acc[mf][nf], ahi[mf], bhi[nf]);
#pragma unroll
            for (int mf = 0; mf < 4; mf++)
#pragma unroll
                for (int nf = 0; nf < 8; nf++)
                    MMA16816(acc[mf][nf], ahi[mf], blo[nf]);
            if (TERMS == 3) {
#pragma unroll
                for (int mf = 0; mf < 4; mf++)
#pragma unroll
                    for (int nf = 0; nf < 8; nf++)
                        MMA16816(acc[mf][nf], alo[mf], bhi[nf]);
            }
        }

        if (c == NC - 1) {
            int col_base = (bxg * TILES + tile) * 128 + warp_n * 64 + (lane & 3) * 2;
            int row_base = by * 256 + warp_m * 64 + (lane >> 2);
            int contrib = warp_n * 4 + (lane & 3);
#pragma unroll
            for (int mf = 0; mf < 4; mf++) {
                float lsA = 0.f, lqA = 0.f, lsB = 0.f, lqB = 0.f;
#pragma unroll
                for (int nf = 0; nf < 8; nf++) {
                    int col = col_base + nf * 8;
                    float b0 = __ldg(bias + col), b1 = __ldg(bias + col + 1);
                    int r0 = row_base + mf * 16;
                    float2 v0 = { acc[mf][nf][0] + b0, acc[mf][nf][1] + b1 };
                    float2 v1 = { acc[mf][nf][2] + b0, acc[mf][nf][3] + b1 };
                    *(float2*)(C + (size_t)r0 * NTOT + col) = v0;
                    *(float2*)(C + (size_t)(r0 + 8) * NTOT + col) = v1;
                    lsA += v0.x + v0.y; lqA += v0.x * v0.x + v0.y * v0.y;
                    lsB += v1.x + v1.y; lqB += v1.x * v1.x + v1.y * v1.y;
                }
                int rA = warp_m * 64 + mf * 16 + (lane >> 2);
                ssum[rA * 8 + contrib] = lsA;
                ssq [rA * 8 + contrib] = lqA;
                ssum[(rA + 8) * 8 + contrib] = lsB;
                ssq [(rA + 8) * 8 + contrib] = lqB;
#pragma unroll
                for (int nf = 0; nf < 8; nf++)
#pragma unroll
                    for (int q = 0; q < 4; q++) acc[mf][nf][q] = 0.0f;
            }
            __syncthreads();
            {
                float s = 0.f, q = 0.f;
#pragma unroll
                for (int p = 0; p < 8; p++) { s += ssum[tid * 8 + p]; q += ssq[tid * 8 + p]; }
                int tcol = bxg * TILES + tile;
                size_t row = (size_t)(by * 256 + tid);
                psum[row * 8 + tcol] = s;   // uniform stride 8
                psq [row * 8 + tcol] = q;
            }
            __syncthreads();
        }
    }
}

// ---------------------------------------------------------------------------
// Fused stats + LIF: one block per (batch, channel-half) -> 512 blocks.
// Each thread handles a float2 (2 channels). Per-channel arithmetic identical
// to the R12/R13-validated body.
// ---------------------------------------------------------------------------
__global__ void __launch_bounds__(256)
lif_fused(const float2* __restrict__ h2p,
          const float* __restrict__ psum, const float* __restrict__ psq,
          const float2* __restrict__ g2, const float2* __restrict__ be2,
          uint32_t* __restrict__ spk2) {
    __shared__ float smean[256], srstd[256];
    int tid = threadIdx.x;
    int b = blockIdx.x >> 1, h = blockIdx.x & 1;
    {
        size_t row = (size_t)b * 256 + tid;
        float s = 0.f, q = 0.f;
#pragma unroll
        for (int p = 0; p < 8; p++) { s += psum[row * 8 + p]; q += psq[row * 8 + p]; }
        float m = s * (1.0f / Hsz);
        float var = fmaxf(q * (1.0f / Hsz) - m * m, 0.0f);
        smean[tid] = m;
        srstd[tid] = 1.0f / sqrtf(var + 1e-5f);
    }
    __syncthreads();

    const int C2 = Hsz / 2;   // 512 float2 per row
    int j = h * 256 + tid;
    float2 gg = g2[j], bb = be2[j];
    float v0 = 0.f, v1 = 0.f;
    size_t base = (size_t)b * Tsz * C2 + j;
#pragma unroll 4
    for (int t = 0; t < Tsz; t++) {
        float2 xi = h2p[base + (size_t)t * C2];
        float m = smean[t], inv = srstd[t];
        float n0 = (xi.x - m) * inv * gg.x + bb.x;
        float n1 = (xi.y - m) * inv * gg.y + bb.y;
        v0 = v0 + (n0 - v0) * 0.5f;
        v1 = v1 + (n1 - v1) * 0.5f;
        float s0 = 0.f, s1 = 0.f;
        if (v0 >= 1.0f) { s0 = 1.0f; v0 = 0.f; }
        if (v1 >= 1.0f) { s1 = 1.0f; v1 = 0.f; }
        __half2 p2 = __halves2half2(__float2half_rn(s0), __float2half_rn(s1));
        spk2[base + (size_t)t * C2] = *(uint32_t*)&p2;
    }
}

// Fused stats + LIF + residual add + sparse split refresh: one block per
// batch -> 256 blocks; each thread a float2 of E. Arithmetic identical.
__global__ void __launch_bounds__(256)
lifadd_fused(const float2* __restrict__ h2p,
             const float* __restrict__ psum, const float* __restrict__ psq,
             const float2* __restrict__ g2, const float2* __restrict__ be2,
             float* __restrict__ x, __half* __restrict__ xhi,
             __half* __restrict__ xlo) {
    __shared__ float smean[256], srstd[256];
    int tid = threadIdx.x;
    int b = blockIdx.x;
    {
        size_t row = (size_t)b * 256 + tid;
        float s = 0.f, q = 0.f;
#pragma unroll
        for (int p = 0; p < 4; p++) { s += psum[row * 8 + p]; q += psq[row * 8 + p]; }
        float m = s * (1.0f / Esz);
        float var = fmaxf(q * (1.0f / Esz) - m * m, 0.0f);
        smean[tid] = m;
        srstd[tid] = 1.0f / sqrtf(var + 1e-5f);
    }
    __syncthreads();

    const int C2 = Esz / 2;   // 256 float2 per row
    int j = tid;
    float2 gg = g2[j], bb = be2[j];
    float v0 = 0.f, v1 = 0.f;
    size_t base = (size_t)b * Tsz * C2 + j;
#pragma unroll 4
    for (int t = 0; t < Tsz; t++) {
        float2 xi = h2p[base + (size_t)t * C2];
        float m = smean[t], inv = srstd[t];
        float n0 = (xi.x - m) * inv * gg.x + bb.x;
        float n1 = (xi.y - m) * inv * gg.y + bb.y;
        v0 = v0 + (n0 - v0) * 0.5f;
        v1 = v1 + (n1 - v1) * 0.5f;
        size_t o = (size_t)b * Tsz * Esz + (size_t)t * Esz + j * 2;
        if (v0 >= 1.0f) {
            v0 = 0.f;
            float xv = x[o] + 1.0f;
            x[o] = xv;
            __half hh = __float2half_rn(xv);
            xhi[o] = hh;
            xlo[o] = __float2half_rn(xv - __half2float(hh));
        }
        if (v1 >= 1.0f) {
            v1 = 0.f;
            float xv = x[o + 1] + 1.0f;
            x[o + 1] = xv;
            __half hh = __float2half_rn(xv);
            xhi[o + 1] = hh;
            xlo[o + 1] = __float2half_rn(xv - __half2float(hh));
        }
    }
}

// ---------------------------------------------------------------------------
// Input projector, tiled (16 rows/block, W2 read once per block)
// ---------------------------------------------------------------------------
#define PR 16
__global__ void __launch_bounds__(256)
proj_kernel(const float* __restrict__ hist,
            const float* __restrict__ W1, const float* __restrict__ b1,
            const float* __restrict__ W2, const float* __restrict__ b2,
            float* __restrict__ out,
            __half* __restrict__ ohi, __half* __restrict__ olo) {
    __shared__ float hs[PR * INsz];
    __shared__ float hpT[HPsz][PR];
    int rb = blockIdx.x * PR;
    int tid = threadIdx.x;

    if (tid < PR * INsz) hs[tid] = hist[(size_t)rb * INsz + tid];
    __syncthreads();

#pragma unroll
    for (int i = 0; i < (PR * HPsz) / 256; i++) {
        int idx = tid + i * 256;
        int r = idx >> 6, cc = idx & 63;
        float a = b1[cc];
#pragma unroll
        for (int k = 0; k < INsz; k++) a += hs[r * INsz + k] * W1[k * HPsz + cc];
        hpT[cc][r] = 0.5f * a * (1.0f + erff(a * 0.70710678118654752440f));
    }
    __syncthreads();

    int c0 = tid * 2;
    float acc[PR][2];
    float bb0 = b2[c0], bb1 = b2[c0 + 1];
#pragma unroll
    for (int r = 0; r < PR; r++) { acc[r][0] = bb0; acc[r][1] = bb1; }

    for (int k = 0; k < HPsz; k++) {
        float2 w = *(const float2*)(W2 + (size_t)k * Esz + c0);
        float4 h0 = *(const float4*)&hpT[k][0];
        float4 h1 = *(const float4*)&hpT[k][4];
        float4 h2 = *(const float4*)&hpT[k][8];
        float4 h3 = *(const float4*)&hpT[k][12];
        float hk[PR] = { h0.x, h0.y, h0.z, h0.w, h1.x, h1.y, h1.z, h1.w,
                         h2.x, h2.y, h2.z, h2.w, h3.x, h3.y, h3.z, h3.w };
#pragma unroll
        for (int r = 0; r < PR; r++) {
            acc[r][0] += hk[r] * w.x;
            acc[r][1] += hk[r] * w.y;
        }
    }

#pragma unroll
    for (int r = 0; r < PR; r++) {
        size_t off = (size_t)(rb + r) * Esz + c0;
        float a0 = acc[r][0], a1 = acc[r][1];
        *(float2*)(out + off) = make_float2(a0, a1);
        __half h0 = __float2half_rn(a0), h1 = __float2half_rn(a1);
        *(__half2*)(ohi + off) = __halves2half2(h0, h1);
        *(__half2*)(olo + off) = __halves2half2(
            __float2half_rn(a0 - __half2float(h0)),
            __float2half_rn(a1 - __half2float(h1)));
    }
}

// Extract last timestep
__global__ void last_kernel(const float* __restrict__ x, float* __restrict__ out) {
    int i = blockIdx.x * blockDim.x + threadIdx.x;
    if (i < Bsz * Esz) {
        int b = i / Esz, e = i % Esz;
        out[i] = x[((size_t)b * Tsz + (Tsz - 1)) * Esz + e];
    }
}

// ---------------------------------------------------------------------------
extern "C" void kernel_launch(void* const* d_in, const int* in_sizes, int n_in,
                              void* d_out, int out_size) {
    const float* hist  = (const float*)d_in[0];
    const float* pW1   = (const float*)d_in[1];
    const float* pb1   = (const float*)d_in[2];
    const float* pW2   = (const float*)d_in[3];
    const float* pb2   = (const float*)d_in[4];
    const float* fc1_w = (const float*)d_in[5];
    const float* fc1_b = (const float*)d_in[6];
    const float* ln1_g = (const float*)d_in[7];
    const float* ln1_b = (const float*)d_in[8];
    const float* fc2_w = (const float*)d_in[9];
    const float* fc2_b = (const float*)d_in[10];
    const float* ln2_g = (const float*)d_in[11];
    const float* ln2_b = (const float*)d_in[12];

    float *x, *h1, *h2, *psum, *psq;
    __half *xhi, *xlo, *spk, *w1hi, *w1lo, *w2hi, *w2lo;
    cudaGetSymbolAddress((void**)&x,    g_x);
    cudaGetSymbolAddress((void**)&h1,   g_h1);
    cudaGetSymbolAddress((void**)&h2,   g_h2);
    cudaGetSymbolAddress((void**)&psum, g_psum);
    cudaGetSymbolAddress((void**)&psq,  g_psq);
    cudaGetSymbolAddress((void**)&xhi,  g_xhi);
    cudaGetSymbolAddress((void**)&xlo,  g_xlo);
    cudaGetSymbolAddress((void**)&spk,  g_spk);
    cudaGetSymbolAddress((void**)&w1hi, g_w1hi);
    cudaGetSymbolAddress((void**)&w1lo, g_w1lo);
    cudaGetSymbolAddress((void**)&w2hi, g_w2hi);
    cudaGetSymbolAddress((void**)&w2lo, g_w2lo);

    auto* gk1 = gemm_hs256<3, 2, Esz, Hsz>;   // GEMM1: 2 N-tiles/CTA
    auto* gk2 = gemm_hs256<2, 1, Hsz, Esz>;   // GEMM2: 1 N-tile/CTA
    cudaFuncSetAttribute(gk1, cudaFuncAttributeMaxDynamicSharedMemorySize, G2<3>::TOT);
    cudaFuncSetAttribute(gk2, cudaFuncAttributeMaxDynamicSharedMemorySize, G2<2>::TOT);

    split_w<<<dim3((Esz * Hsz + 255) / 256, Dsz), 256>>>(fc1_w, w1hi, w1lo, Esz, Hsz);
    split_w<<<dim3((Hsz * Esz + 255) / 256, Dsz), 256>>>(fc2_w, w2hi, w2lo, Hsz, Esz);

    proj_kernel<<<ROWS / PR, 256>>>(hist, pW1, pb1, pW2, pb2, x, xhi, xlo);

    for (int d = 0; d < Dsz; d++) {
        size_t o1 = (size_t)d * Hsz * Esz;
        size_t o2 = (size_t)d * Esz * Hsz;

        gk1<<<dim3(Hsz / 128 / 2, ROWS / 256), 256, G2<3>::TOT>>>(
            xhi, xlo, w1hi + o1, w1lo + o1, fc1_b + d * Hsz, h1, psum, psq);
        lif_fused<<<Bsz * 2, 256>>>(
            (const float2*)h1, psum, psq, (const float2*)(ln1_g + d * Hsz),
            (const float2*)(ln1_b + d * Hsz), (uint32_t*)spk);

        gk2<<<dim3(Esz / 128, ROWS / 256), 256, G2<2>::TOT>>>(
            spk, spk, w2hi + o2, w2lo + o2, fc2_b + d * Esz, h2, psum, psq);
        lifadd_fused<<<Bsz, 256>>>(
            (const float2*)h2, psum, psq, (const float2*)(ln2_g + d * Esz),
            (const float2*)(ln2_b + d * Esz), x, xhi, xlo);
    }

    last_kernel<<<(Bsz * Esz + 255) / 256, 256>>>(x, (float*)d_out);
}

// round 15
// speedup vs baseline: 1.3620x; 1.0594x over previous
#include <cuda_runtime.h>
#include <cuda_fp16.h>
#include <math.h>
#include <stdint.h>

// Problem dims
#define Bsz  256
#define Tsz  256
#define INsz 4
#define HPsz 64
#define Esz  512
#define Hsz  1024
#define Dsz  4
#define ROWS (Bsz * Tsz)   // 65536

// ---------------------------------------------------------------------------
// Scratch (device globals; no allocation allowed)
// ---------------------------------------------------------------------------
__device__ float  g_x  [(size_t)ROWS * Esz];
__device__ __half g_xhi[(size_t)ROWS * Esz];
__device__ __half g_xlo[(size_t)ROWS * Esz];
__device__ float  g_h1 [(size_t)ROWS * Hsz];
__device__ __half g_spk[(size_t)ROWS * Hsz];
__device__ float  g_h2 [(size_t)ROWS * Esz];
__device__ float  g_psum[(size_t)ROWS * 8];   // stride 8 for BOTH gemms
__device__ float  g_psq [(size_t)ROWS * 8];
__device__ __half g_w1hi[(size_t)Dsz * Hsz * Esz];
__device__ __half g_w1lo[(size_t)Dsz * Hsz * Esz];
__device__ __half g_w2hi[(size_t)Dsz * Esz * Hsz];
__device__ __half g_w2lo[(size_t)Dsz * Esz * Hsz];

// ---------------------------------------------------------------------------
// Helpers
// ---------------------------------------------------------------------------
__device__ __forceinline__ uint32_t sw128(uint32_t b) { return b ^ ((b >> 3) & 0x70); }

__device__ __forceinline__ uint32_t s2u(const void* p) {
    uint32_t a;
    asm("{ .reg .u64 t; cvta.to.shared.u64 t, %1; cvt.u32.u64 %0, t; }" : "=r"(a) : "l"(p));
    return a;
}

__device__ __forceinline__ void cp16(uint32_t saddr, const void* g) {
    asm volatile("cp.async.cg.shared.global [%0], [%1], 16;" :: "r"(saddr), "l"(g));
}

#define LDSM4(r0, r1, r2, r3, addr)                                           \
    asm volatile("ldmatrix.sync.aligned.m8n8.x4.shared.b16 {%0,%1,%2,%3}, [%4];" \
                 : "=r"(r0), "=r"(r1), "=r"(r2), "=r"(r3) : "r"(addr))

#define MMA16816(d, a, b)                                                     \
    asm volatile(                                                             \
        "mma.sync.aligned.m16n8k16.row.col.f32.f16.f16.f32 "                  \
        "{%0,%1,%2,%3},{%4,%5,%6,%7},{%8,%9},{%0,%1,%2,%3};"                  \
        : "+f"((d)[0]), "+f"((d)[1]), "+f"((d)[2]), "+f"((d)[3])              \
        : "r"((a)[0]), "r"((a)[1]), "r"((a)[2]), "r"((a)[3]),                 \
          "r"((b)[0]), "r"((b)[1]))

// ---------------------------------------------------------------------------
// Split+transpose weights
// ---------------------------------------------------------------------------
__global__ void split_w(const float* __restrict__ W, __half* __restrict__ hi,
                        __half* __restrict__ lo, int K, int N) {
    int idx = blockIdx.x * blockDim.x + threadIdx.x;
    if (idx >= K * N) return;
    size_t lofs = (size_t)blockIdx.y * K * N;
    int k = idx / N, n = idx % N;
    float w = W[lofs + idx];
    __half h = __float2half_rn(w);
    hi[lofs + (size_t)n * K + k] = h;
    lo[lofs + (size_t)n * K + k] = __float2half_rn(w - __half2float(h));
}

// ---------------------------------------------------------------------------
// GEMM: C = Ahi@Bhi^T + Ahi@Blo^T (+ Alo@Bhi^T) + bias; epilogue emits
// per-tile LN partials (stride-8). CTA 256x128, warp 64x64, BK=64, 2-stage.
// ---------------------------------------------------------------------------
template <int TERMS> struct G2 {
    static constexpr int AHI = 0;
    static constexpr int ALO = 32768;
    static constexpr int BHI = (TERMS == 3) ? 65536 : 32768;
    static constexpr int BLO = BHI + 16384;
    static constexpr int STG = BLO + 16384;      // 96 KB / 64 KB
    static constexpr int STATS = 2 * STG;
    static constexpr int TOT = STATS + 16384;    // 208 KB / 144 KB
};

template <int TERMS, int KK>
__device__ __forceinline__ void load_stage256(uint32_t sbase,
                                              const __half* A, const __half* Al,
                                              const __half* B, const __half* Bl,
                                              int k0, int tid) {
#pragma unroll
    for (int it = 0; it < 8; it++) {
        int idx = tid + it * 256;
        int r = idx >> 3, c = idx & 7;
        uint32_t so = sw128((uint32_t)(r * 128 + c * 16));
        size_t go = (size_t)r * KK + k0 + c * 8;
        cp16(sbase + G2<TERMS>::AHI + so, A + go);
        if (TERMS == 3) cp16(sbase + G2<TERMS>::ALO + so, Al + go);
    }
#pragma unroll
    for (int it = 0; it < 4; it++) {
        int idx = tid + it * 256;
        int r = idx >> 3, c = idx & 7;
        uint32_t so = sw128((uint32_t)(r * 128 + c * 16));
        size_t go = (size_t)r * KK + k0 + c * 8;
        cp16(sbase + G2<TERMS>::BHI + so, B + go);
        cp16(sbase + G2<TERMS>::BLO + so, Bl + go);
    }
    asm volatile("cp.async.commit_group;" ::: "memory");
}

template <int TERMS, int TILES, int KK, int NTOT>
__global__ void __launch_bounds__(256, 1)
gemm_hs256(const __half* __restrict__ Ahi, const __half* __restrict__ Alo,
           const __half* __restrict__ Bhi, const __half* __restrict__ Blo,
           const float* __restrict__ bias, float* __restrict__ C,
           float* __restrict__ psum, float* __restrict__ psq) {
    using GG = G2<TERMS>;
    extern __shared__ char smc[];
    uint32_t sb = s2u(smc);
    float* ssum = (float*)(smc + GG::STATS);
    float* ssq  = (float*)(smc + GG::STATS + 8192);
    int tid = threadIdx.x;
    int wid = tid >> 5, lane = tid & 31;
    int warp_m = wid >> 1, warp_n = wid & 1;
    int bxg = blockIdx.x, by = blockIdx.y;
    int row_in = lane & 7, grp = lane >> 3;

    constexpr int NC = KK / 64;
    constexpr int TC = TILES * NC;

    const __half* Ah = Ahi + (size_t)(by * 256) * KK;
    const __half* Al = Alo + (size_t)(by * 256) * KK;

    float acc[4][8][4] = {};
    uint32_t ahi[4][4], alo[4][4], bhi[8][2], blo[8][2];

    {
        const __half* Bh0 = Bhi + (size_t)(bxg * TILES * 128) * KK;
        const __half* Bl0 = Blo + (size_t)(bxg * TILES * 128) * KK;
        load_stage256<TERMS, KK>(sb, Ah, Al, Bh0, Bl0, 0, tid);
    }

    for (int g = 0; g < TC; g++) {
        int tile = g / NC, c = g % NC;
        asm volatile("cp.async.wait_group 0;" ::: "memory");
        __syncthreads();

        int g1 = g + 1;
        if (g1 < TC) {
            int t1 = g1 / NC, c1 = g1 % NC;
            const __half* Bh1 = Bhi + (size_t)((bxg * TILES + t1) * 128) * KK;
            const __half* Bl1 = Blo + (size_t)((bxg * TILES + t1) * 128) * KK;
            load_stage256<TERMS, KK>(sb + (g1 & 1) * GG::STG, Ah, Al, Bh1, Bl1, c1 * 64, tid);
        }

        uint32_t stg = sb + (g & 1) * GG::STG;
#pragma unroll
        for (int ks = 0; ks < 4; ks++) {
#pragma unroll
            for (int mf = 0; mf < 4; mf++) {
                int r = warp_m * 64 + mf * 16 + (grp & 1) * 8 + row_in;
                int kb = ks * 32 + (grp >> 1) * 16;
                uint32_t off = sw128((uint32_t)(r * 128 + kb));
                LDSM4(ahi[mf][0], ahi[mf][1], ahi[mf][2], ahi[mf][3], stg + GG::AHI + off);
                if (TERMS == 3)
                    LDSM4(alo[mf][0], alo[mf][1], alo[mf][2], alo[mf][3],
                          stg + GG::ALO + off);
            }
#pragma unroll
            for (int p = 0; p < 4; p++) {
                int r = warp_n * 64 + p * 16 + (grp >> 1) * 8 + row_in;
                int kb = ks * 32 + (grp & 1) * 16;
                uint32_t off = sw128((uint32_t)(r * 128 + kb));
                uint32_t t0, t1, t2, t3;
                LDSM4(t0, t1, t2, t3, stg + GG::BHI + off);
                bhi[2 * p][0] = t0; bhi[2 * p][1] = t1;
                bhi[2 * p + 1][0] = t2; bhi[2 * p + 1][1] = t3;
                LDSM4(t0, t1, t2, t3, stg + GG::BLO + off);
                blo[2 * p][0] = t0; blo[2 * p][1] = t1;
                blo[2 * p + 1][0] = t2; blo[2 * p + 1][1] = t3;
            }
            // per-acc order: hibhi -> hiblo -> lobhi (unchanged)
#pragma unroll
            for (int mf = 0; mf < 4; mf++)
#pragma unroll
                for (int nf = 0; nf < 8; nf++)
                    MMA16816(acc[mf][nf], ahi[mf], bhi[nf]);
#pragma unroll
            for (int mf = 0; mf < 4; mf++)
#pragma unroll
                for (int nf = 0; nf < 8; nf++)
                    MMA16816(acc[mf][nf], ahi[mf], blo[nf]);
            if (TERMS == 3) {
#pragma unroll
                for (int mf = 0; mf < 4; mf++)
#pragma unroll
                    for (int nf = 0; nf < 8; nf++)
                        MMA16816(acc[mf][nf], alo[mf], bhi[nf]);
            }
        }

        if (c == NC - 1) {
            int col_base = (bxg * TILES + tile) * 128 + warp_n * 64 + (lane & 3) * 2;
            int row_base = by * 256 + warp_m * 64 + (lane >> 2);
            int contrib = warp_n * 4 + (lane & 3);
#pragma unroll
            for (int mf = 0; mf < 4; mf++) {
                float lsA = 0.f, lqA = 0.f, lsB = 0.f, lqB = 0.f;
#pragma unroll
                for (int nf = 0; nf < 8; nf++) {
                    int col = col_base + nf * 8;
                    float b0 = __ldg(bias + col), b1 = __ldg(bias + col + 1);
                    int r0 = row_base + mf * 16;
                    float2 v0 = { acc[mf][nf][0] + b0, acc[mf][nf][1] + b1 };
                    float2 v1 = { acc[mf][nf][2] + b0, acc[mf][nf][3] + b1 };
                    *(float2*)(C + (size_t)r0 * NTOT + col) = v0;
                    *(float2*)(C + (size_t)(r0 + 8) * NTOT + col) = v1;
                    lsA += v0.x + v0.y; lqA += v0.x * v0.x + v0.y * v0.y;
                    lsB += v1.x + v1.y; lqB += v1.x * v1.x + v1.y * v1.y;
                }
                int rA = warp_m * 64 + mf * 16 + (lane >> 2);
                ssum[rA * 8 + contrib] = lsA;
                ssq [rA * 8 + contrib] = lqA;
                ssum[(rA + 8) * 8 + contrib] = lsB;
                ssq [(rA + 8) * 8 + contrib] = lqB;
#pragma unroll
                for (int nf = 0; nf < 8; nf++)
#pragma unroll
                    for (int q = 0; q < 4; q++) acc[mf][nf][q] = 0.0f;
            }
            __syncthreads();
            {
                float s = 0.f, q = 0.f;
#pragma unroll
                for (int p = 0; p < 8; p++) { s += ssum[tid * 8 + p]; q += ssq[tid * 8 + p]; }
                int tcol = bxg * TILES + tile;
                size_t row = (size_t)(by * 256 + tid);
                psum[row * 8 + tcol] = s;   // uniform stride 8
                psq [row * 8 + tcol] = q;
            }
            __syncthreads();
        }
    }
}

// ---------------------------------------------------------------------------
// Fused stats + LIF: one block per (batch, channel-quarter) -> 1024 blocks.
// Each thread handles ONE channel (scalar). Per-channel arithmetic identical
// to the validated R13/R14 body.
// ---------------------------------------------------------------------------
__global__ void __launch_bounds__(256)
lif_fused(const float* __restrict__ h,
          const float* __restrict__ psum, const float* __restrict__ psq,
          const float* __restrict__ gam, const float* __restrict__ bet,
          __half* __restrict__ spk) {
    __shared__ float smean[256], srstd[256];
    int tid = threadIdx.x;
    int b = blockIdx.x >> 2, qh = blockIdx.x & 3;
    {
        size_t row = (size_t)b * 256 + tid;
        float s = 0.f, q = 0.f;
#pragma unroll
        for (int p = 0; p < 8; p++) { s += psum[row * 8 + p]; q += psq[row * 8 + p]; }
        float m = s * (1.0f / Hsz);
        float var = fmaxf(q * (1.0f / Hsz) - m * m, 0.0f);
        smean[tid] = m;
        srstd[tid] = 1.0f / sqrtf(var + 1e-5f);
    }
    __syncthreads();

    int j = qh * 256 + tid;
    float gg = gam[j], bb = bet[j];
    float v = 0.f;
    size_t base = (size_t)b * Tsz * Hsz + j;
#pragma unroll 4
    for (int t = 0; t < Tsz; t++) {
        float xi = h[base + (size_t)t * Hsz];
        float m = smean[t], inv = srstd[t];
        float n = (xi - m) * inv * gg + bb;
        v = v + (n - v) * 0.5f;
        float sp = 0.f;
        if (v >= 1.0f) { sp = 1.0f; v = 0.f; }
        spk[base + (size_t)t * Hsz] = __float2half_rn(sp);
    }
}

// Fused stats + LIF + residual add + sparse split refresh: one block per
// (batch, channel-half) -> 512 blocks; scalar channel per thread.
__global__ void __launch_bounds__(256)
lifadd_fused(const float* __restrict__ h,
             const float* __restrict__ psum, const float* __restrict__ psq,
             const float* __restrict__ gam, const float* __restrict__ bet,
             float* __restrict__ x, __half* __restrict__ xhi,
             __half* __restrict__ xlo) {
    __shared__ float smean[256], srstd[256];
    int tid = threadIdx.x;
    int b = blockIdx.x >> 1, hh = blockIdx.x & 1;
    {
        size_t row = (size_t)b * 256 + tid;
        float s = 0.f, q = 0.f;
#pragma unroll
        for (int p = 0; p < 4; p++) { s += psum[row * 8 + p]; q += psq[row * 8 + p]; }
        float m = s * (1.0f / Esz);
        float var = fmaxf(q * (1.0f / Esz) - m * m, 0.0f);
        smean[tid] = m;
        srstd[tid] = 1.0f / sqrtf(var + 1e-5f);
    }
    __syncthreads();

    int j = hh * 256 + tid;
    float gg = gam[j], bb = bet[j];
    float v = 0.f;
    size_t base = (size_t)b * Tsz * Esz + j;
#pragma unroll 4
    for (int t = 0; t < Tsz; t++) {
        float xi = h[base + (size_t)t * Esz];
        float m = smean[t], inv = srstd[t];
        float n = (xi - m) * inv * gg + bb;
        v = v + (n - v) * 0.5f;
        if (v >= 1.0f) {
            v = 0.f;
            size_t o = base + (size_t)t * Esz;
            float xv = x[o] + 1.0f;
            x[o] = xv;
            __half hv = __float2half_rn(xv);
            xhi[o] = hv;
            xlo[o] = __float2half_rn(xv - __half2float(hv));
        }
    }
}

// ---------------------------------------------------------------------------
// Input projector, tiled (16 rows/block, W2 read once per block)
// ---------------------------------------------------------------------------
#define PR 16
__global__ void __launch_bounds__(256)
proj_kernel(const float* __restrict__ hist,
            const float* __restrict__ W1, const float* __restrict__ b1,
            const float* __restrict__ W2, const float* __restrict__ b2,
            float* __restrict__ out,
            __half* __restrict__ ohi, __half* __restrict__ olo) {
    __shared__ float hs[PR * INsz];
    __shared__ float hpT[HPsz][PR];
    int rb = blockIdx.x * PR;
    int tid = threadIdx.x;

    if (tid < PR * INsz) hs[tid] = hist[(size_t)rb * INsz + tid];
    __syncthreads();

#pragma unroll
    for (int i = 0; i < (PR * HPsz) / 256; i++) {
        int idx = tid + i * 256;
        int r = idx >> 6, cc = idx & 63;
        float a = b1[cc];
#pragma unroll
        for (int k = 0; k < INsz; k++) a += hs[r * INsz + k] * W1[k * HPsz + cc];
        hpT[cc][r] = 0.5f * a * (1.0f + erff(a * 0.70710678118654752440f));
    }
    __syncthreads();

    int c0 = tid * 2;
    float acc[PR][2];
    float bb0 = b2[c0], bb1 = b2[c0 + 1];
#pragma unroll
    for (int r = 0; r < PR; r++) { acc[r][0] = bb0; acc[r][1] = bb1; }

    for (int k = 0; k < HPsz; k++) {
        float2 w = *(const float2*)(W2 + (size_t)k * Esz + c0);
        float4 h0 = *(const float4*)&hpT[k][0];
        float4 h1 = *(const float4*)&hpT[k][4];
        float4 h2 = *(const float4*)&hpT[k][8];
        float4 h3 = *(const float4*)&hpT[k][12];
        float hk[PR] = { h0.x, h0.y, h0.z, h0.w, h1.x, h1.y, h1.z, h1.w,
                         h2.x, h2.y, h2.z, h2.w, h3.x, h3.y, h3.z, h3.w };
#pragma unroll
        for (int r = 0; r < PR; r++) {
            acc[r][0] += hk[r] * w.x;
            acc[r][1] += hk[r] * w.y;
        }
    }

#pragma unroll
    for (int r = 0; r < PR; r++) {
        size_t off = (size_t)(rb + r) * Esz + c0;
        float a0 = acc[r][0], a1 = acc[r][1];
        *(float2*)(out + off) = make_float2(a0, a1);
        __half h0 = __float2half_rn(a0), h1 = __float2half_rn(a1);
        *(__half2*)(ohi + off) = __halves2half2(h0, h1);
        *(__half2*)(olo + off) = __halves2half2(
            __float2half_rn(a0 - __half2float(h0)),
            __float2half_rn(a1 - __half2float(h1)));
    }
}

// Extract last timestep
__global__ void last_kernel(const float* __restrict__ x, float* __restrict__ out) {
    int i = blockIdx.x * blockDim.x + threadIdx.x;
    if (i < Bsz * Esz) {
        int b = i / Esz, e = i % Esz;
        out[i] = x[((size_t)b * Tsz + (Tsz - 1)) * Esz + e];
    }
}

// ---------------------------------------------------------------------------
extern "C" void kernel_launch(void* const* d_in, const int* in_sizes, int n_in,
                              void* d_out, int out_size) {
    const float* hist  = (const float*)d_in[0];
    const float* pW1   = (const float*)d_in[1];
    const float* pb1   = (const float*)d_in[2];
    const float* pW2   = (const float*)d_in[3];
    const float* pb2   = (const float*)d_in[4];
    const float* fc1_w = (const float*)d_in[5];
    const float* fc1_b = (const float*)d_in[6];
    const float* ln1_g = (const float*)d_in[7];
    const float* ln1_b = (const float*)d_in[8];
    const float* fc2_w = (const float*)d_in[9];
    const float* fc2_b = (const float*)d_in[10];
    const float* ln2_g = (const float*)d_in[11];
    const float* ln2_b = (const float*)d_in[12];

    float *x, *h1, *h2, *psum, *psq;
    __half *xhi, *xlo, *spk, *w1hi, *w1lo, *w2hi, *w2lo;
    cudaGetSymbolAddress((void**)&x,    g_x);
    cudaGetSymbolAddress((void**)&h1,   g_h1);
    cudaGetSymbolAddress((void**)&h2,   g_h2);
    cudaGetSymbolAddress((void**)&psum, g_psum);
    cudaGetSymbolAddress((void**)&psq,  g_psq);
    cudaGetSymbolAddress((void**)&xhi,  g_xhi);
    cudaGetSymbolAddress((void**)&xlo,  g_xlo);
    cudaGetSymbolAddress((void**)&spk,  g_spk);
    cudaGetSymbolAddress((void**)&w1hi, g_w1hi);
    cudaGetSymbolAddress((void**)&w1lo, g_w1lo);
    cudaGetSymbolAddress((void**)&w2hi, g_w2hi);
    cudaGetSymbolAddress((void**)&w2lo, g_w2lo);

    auto* gk1 = gemm_hs256<3, 2, Esz, Hsz>;   // GEMM1: 2 N-tiles/CTA
    auto* gk2 = gemm_hs256<2, 1, Hsz, Esz>;   // GEMM2: 1 N-tile/CTA
    cudaFuncSetAttribute(gk1, cudaFuncAttributeMaxDynamicSharedMemorySize, G2<3>::TOT);
    cudaFuncSetAttribute(gk2, cudaFuncAttributeMaxDynamicSharedMemorySize, G2<2>::TOT);

    split_w<<<dim3((Esz * Hsz + 255) / 256, Dsz), 256>>>(fc1_w, w1hi, w1lo, Esz, Hsz);
    split_w<<<dim3((Hsz * Esz + 255) / 256, Dsz), 256>>>(fc2_w, w2hi, w2lo, Hsz, Esz);

    proj_kernel<<<ROWS / PR, 256>>>(hist, pW1, pb1, pW2, pb2, x, xhi, xlo);

    for (int d = 0; d < Dsz; d++) {
        size_t o1 = (size_t)d * Hsz * Esz;
        size_t o2 = (size_t)d * Esz * Hsz;

        gk1<<<dim3(Hsz / 128 / 2, ROWS / 256), 256, G2<3>::TOT>>>(
            xhi, xlo, w1hi + o1, w1lo + o1, fc1_b + d * Hsz, h1, psum, psq);
        lif_fused<<<Bsz * 4, 256>>>(
            h1, psum, psq, ln1_g + d * Hsz, ln1_b + d * Hsz, spk);

        gk2<<<dim3(Esz / 128, ROWS / 256), 256, G2<2>::TOT>>>(
            spk, spk, w2hi + o2, w2lo + o2, fc2_b + d * Esz, h2, psum, psq);
        lifadd_fused<<<Bsz * 2, 256>>>(
            h2, psum, psq, ln2_g + d * Esz, ln2_b + d * Esz, x, xhi, xlo);
    }

    last_kernel<<<(Bsz * Esz + 255) / 256, 256>>>(x, (float*)d_out);
}